// round 6
// baseline (speedup 1.0000x reference)
#include <cuda_runtime.h>
#include <cstdint>

#define NNODES  50000
#define NPAD    50048      // 391 * 128
#define NEDGE   500000
#define DIM     128
#define DIM2    256
#define NLAYERS 5
#define NGRAPH  128

// ---------------- scratch (static device globals; zero-initialized) ----------------
__device__ float g_h [(size_t)NPAD * DIM];
__device__ float g_z [(size_t)NPAD * DIM];
__device__ float g_z1[(size_t)NPAD * DIM2];
__device__ float g_sum1[DIM2], g_sq1[DIM2], g_aff1[2 * DIM2];
__device__ float g_sum2[DIM ], g_sq2[DIM ], g_aff2[2 * DIM ];
// pre-transposed [N,K] tf32-split weights
__device__ float g_w1h[(size_t)NLAYERS * DIM2 * DIM];
__device__ float g_w1l[(size_t)NLAYERS * DIM2 * DIM];
__device__ float g_w2h[(size_t)NLAYERS * DIM * DIM2];
__device__ float g_w2l[(size_t)NLAYERS * DIM * DIM2];

// ---------------- PTX helpers (all baseline, non-'a' features) ----------------
__device__ __forceinline__ void red_add_v4(float* p, float4 v) {
    asm volatile("red.global.add.v4.f32 [%0], {%1, %2, %3, %4};"
                 :: "l"(p), "f"(v.x), "f"(v.y), "f"(v.z), "f"(v.w) : "memory");
}
__device__ __forceinline__ float to_tf32(float x) {
    uint32_t u; asm("cvt.rna.tf32.f32 %0, %1;" : "=r"(u) : "f"(x));
    return __uint_as_float(u);
}
__device__ __forceinline__ void mma_tf32(float c[4],
                                         uint32_t a0, uint32_t a1, uint32_t a2, uint32_t a3,
                                         uint32_t b0, uint32_t b1) {
    asm volatile(
        "mma.sync.aligned.m16n8k8.row.col.f32.tf32.tf32.f32 "
        "{%0,%1,%2,%3}, {%4,%5,%6,%7}, {%8,%9}, {%0,%1,%2,%3};"
        : "+f"(c[0]), "+f"(c[1]), "+f"(c[2]), "+f"(c[3])
        : "r"(a0), "r"(a1), "r"(a2), "r"(a3), "r"(b0), "r"(b1));
}

// ---------------- layer-0 init ----------------
__global__ void k_init(const int* __restrict__ x, const float* __restrict__ atom_emb) {
    int i = blockIdx.x * blockDim.x + threadIdx.x;
    if (i >= NNODES * 32) return;
    int n = i >> 5, c = (i & 31) * 4;
    int a = __ldg(x + n);
    float4 v = *(const float4*)(atom_emb + (size_t)a * DIM + c);
    *(float4*)(g_h + (size_t)n * DIM + c) = v;
    *(float4*)(g_z + (size_t)n * DIM + c) = v;
}

// ---------------- weight prep: transpose to [N,K] and tf32-split (once per replay) ----------------
__global__ void k_prep(const float* __restrict__ W1, const float* __restrict__ W2) {
    const int TOT = NLAYERS * DIM * DIM2;
    int i = blockIdx.x * blockDim.x + threadIdx.x;
    if (i < TOT) {
        int l = i / (DIM2 * DIM), r = i % (DIM2 * DIM);
        int n = r / DIM, k = r % DIM;
        float v = W1[(size_t)l * DIM * DIM2 + (size_t)k * DIM2 + n];
        float hi = to_tf32(v);
        g_w1h[i] = hi; g_w1l[i] = to_tf32(v - hi);
    } else if (i < 2 * TOT) {
        int j = i - TOT;
        int l = j / (DIM * DIM2), r = j % (DIM * DIM2);
        int n = r / DIM2, k = r % DIM2;
        float v = W2[(size_t)l * DIM2 * DIM + (size_t)k * DIM + n];
        float hi = to_tf32(v);
        g_w2h[j] = hi; g_w2l[j] = to_tf32(v - hi);
    }
}

// ---------------- message passing ----------------
__global__ void k_scatter(const int* __restrict__ src, const int* __restrict__ dst,
                          const int* __restrict__ eattr, const float* __restrict__ bond_emb) {
    int e = blockIdx.x * 8 + (threadIdx.x >> 5);
    if (e >= NEDGE) return;
    int lane = threadIdx.x & 31;
    int s = __ldg(src + e), d = __ldg(dst + e), a = __ldg(eattr + e);
    float4 hv = *(const float4*)(g_h + (size_t)s * DIM + lane * 4);
    float4 ev = *(const float4*)(bond_emb + (size_t)a * DIM + lane * 4);
    float4 m;
    m.x = fmaxf(hv.x + ev.x, 0.f);
    m.y = fmaxf(hv.y + ev.y, 0.f);
    m.z = fmaxf(hv.z + ev.z, 0.f);
    m.w = fmaxf(hv.w + ev.w, 0.f);
    red_add_v4(g_z + (size_t)d * DIM + lane * 4, m);
}

__global__ void k_zero_stats() {
    int t = threadIdx.x;
    if (t < DIM2) { g_sum1[t] = 0.f; g_sq1[t] = 0.f; }
    if (t < DIM)  { g_sum2[t] = 0.f; g_sq2[t] = 0.f; }
}

// ---------------- tensor GEMM via mma.sync tf32 (3x split): C = A @ Wt^T + bias ----------------
// A [NPAD,K] fp32; Wt hi/lo [NC,K] pre-split. CTA tile 128x128, 8 warps (2m x 4n),
// warp tile 64x32 = 4x4 m16n8k8 fragments. K staged in 32-wide smem chunks.
// smem floats, stride 36 per row (bank-conflict-free fragment loads):
//   Ah[128*36] @0   Al @4608   Bh @9216   Bl @13824   sbias @18432(128)  saff @18560(2K)
#define SMEM_FLOATS (18432/4*4)   // placeholder; real layout below in floats
#define SMEM_BYTES  (4 * (4 * 4608 + 128 + 512))   // 4 tiles + bias + aff = 76288 B

template<int K, int NC, bool AFF>
__global__ void __launch_bounds__(256, 2)
k_gemm_t(const float* __restrict__ A,
         const float* __restrict__ Bh, const float* __restrict__ Bl,
         const float* __restrict__ bias, const float* __restrict__ aff,
         float* __restrict__ C, float* __restrict__ gsum, float* __restrict__ gsq) {
    extern __shared__ float sm[];
    float* Ah_s   = sm;                 // [128][36]
    float* Al_s   = sm + 4608;
    float* Bh_s   = sm + 9216;
    float* Bl_s   = sm + 13824;
    float* sbias  = sm + 18432;         // 128
    float* saff   = sm + 18560;         // up to 512

    const int tid  = threadIdx.x;
    const int lane = tid & 31, wid = tid >> 5;
    const int g = lane >> 2, tg = lane & 3;
    const int wm = wid >> 2, wn = wid & 3;            // 2 x 4 warp grid
    const int bm0 = blockIdx.x * 128, bn0 = blockIdx.y * 128;

    if (tid < 128) sbias[tid] = bias[bn0 + tid];
    if (AFF) for (int t = tid; t < 2 * K; t += 256) saff[t] = aff[t];

    // staging mapping: 2 threads per row, 16 k-cols each
    const int s_row = tid >> 1;
    const int s_cb  = (tid & 1) * 16;
    const float* Ag  = A  + (size_t)(bm0 + s_row) * K + s_cb;
    const float* Bgh = Bh + (size_t)(bn0 + s_row) * K + s_cb;
    const float* Bgl = Bl + (size_t)(bn0 + s_row) * K + s_cb;

    float acc[4][4][4];
    #pragma unroll
    for (int i = 0; i < 4; i++)
        #pragma unroll
        for (int j = 0; j < 4; j++)
            #pragma unroll
            for (int r = 0; r < 4; r++) acc[i][j][r] = 0.f;

    const int mrow = wm * 64;           // warp row base in tile
    const int ncol = wn * 32;           // warp col base in tile

    #pragma unroll 1
    for (int ch = 0; ch < K / 32; ch++) {
        const int kc = ch * 32;
        __syncthreads();                 // previous chunk's fragment reads done
        // ---- stage A (affine+relu, split) and B (pre-split copy) ----
        #pragma unroll
        for (int j = 0; j < 4; j++) {
            float4 v = *(const float4*)(Ag + kc + j * 4);
            if (AFF) {
                const float* sc = saff + kc + s_cb + j * 4;
                const float* sh = sc + K;
                v.x = fmaxf(fmaf(v.x, sc[0], sh[0]), 0.f);
                v.y = fmaxf(fmaf(v.y, sc[1], sh[1]), 0.f);
                v.z = fmaxf(fmaf(v.z, sc[2], sh[2]), 0.f);
                v.w = fmaxf(fmaf(v.w, sc[3], sh[3]), 0.f);
            }
            float4 hi, lo;
            hi.x = to_tf32(v.x); lo.x = to_tf32(v.x - hi.x);
            hi.y = to_tf32(v.y); lo.y = to_tf32(v.y - hi.y);
            hi.z = to_tf32(v.z); lo.z = to_tf32(v.z - hi.z);
            hi.w = to_tf32(v.w); lo.w = to_tf32(v.w - hi.w);
            *(float4*)(Ah_s + s_row * 36 + s_cb + j * 4) = hi;
            *(float4*)(Al_s + s_row * 36 + s_cb + j * 4) = lo;
            float4 bh4 = *(const float4*)(Bgh + kc + j * 4);
            float4 bl4 = *(const float4*)(Bgl + kc + j * 4);
            *(float4*)(Bh_s + s_row * 36 + s_cb + j * 4) = bh4;
            *(float4*)(Bl_s + s_row * 36 + s_cb + j * 4) = bl4;
        }
        __syncthreads();

        // ---- 4 k8-steps of MMA ----
        #pragma unroll
        for (int ks = 0; ks < 4; ks++) {
            const int k0 = ks * 8;
            uint32_t bhf[4][2], blf[4][2];
            #pragma unroll
            for (int j = 0; j < 4; j++) {
                int nb = (ncol + j * 8 + g) * 36 + k0 + tg;
                bhf[j][0] = __float_as_uint(Bh_s[nb]);
                bhf[j][1] = __float_as_uint(Bh_s[nb + 4]);
                blf[j][0] = __float_as_uint(Bl_s[nb]);
                blf[j][1] = __float_as_uint(Bl_s[nb + 4]);
            }
            #pragma unroll
            for (int i = 0; i < 4; i++) {
                int rb = (mrow + i * 16 + g) * 36 + k0 + tg;
                uint32_t ah0 = __float_as_uint(Ah_s[rb]);
                uint32_t ah1 = __float_as_uint(Ah_s[rb + 8 * 36]);
                uint32_t ah2 = __float_as_uint(Ah_s[rb + 4]);
                uint32_t ah3 = __float_as_uint(Ah_s[rb + 8 * 36 + 4]);
                uint32_t al0 = __float_as_uint(Al_s[rb]);
                uint32_t al1 = __float_as_uint(Al_s[rb + 8 * 36]);
                uint32_t al2 = __float_as_uint(Al_s[rb + 4]);
                uint32_t al3 = __float_as_uint(Al_s[rb + 8 * 36 + 4]);
                #pragma unroll
                for (int j = 0; j < 4; j++) {
                    mma_tf32(acc[i][j], ah0, ah1, ah2, ah3, bhf[j][0], bhf[j][1]);
                    mma_tf32(acc[i][j], ah0, ah1, ah2, ah3, blf[j][0], blf[j][1]);
                    mma_tf32(acc[i][j], al0, al1, al2, al3, bhf[j][0], bhf[j][1]);
                }
            }
        }
    }

    // ---- epilogue: bias, store, masked column stats ----
    float ps[4][2], pq[4][2];
    #pragma unroll
    for (int j = 0; j < 4; j++) { ps[j][0] = ps[j][1] = pq[j][0] = pq[j][1] = 0.f; }

    #pragma unroll
    for (int i = 0; i < 4; i++) {
        int r0 = bm0 + mrow + i * 16 + g;
        int r1 = r0 + 8;
        #pragma unroll
        for (int j = 0; j < 4; j++) {
            int lc = ncol + j * 8 + 2 * tg;
            float b0 = sbias[lc], b1 = sbias[lc + 1];
            float v0 = acc[i][j][0] + b0, v1 = acc[i][j][1] + b1;
            float v2 = acc[i][j][2] + b0, v3 = acc[i][j][3] + b1;
            *(float2*)(C + (size_t)r0 * NC + bn0 + lc) = make_float2(v0, v1);
            *(float2*)(C + (size_t)r1 * NC + bn0 + lc) = make_float2(v2, v3);
            if (r0 < NNODES) {
                ps[j][0] += v0; pq[j][0] += v0 * v0;
                ps[j][1] += v1; pq[j][1] += v1 * v1;
            }
            if (r1 < NNODES) {
                ps[j][0] += v2; pq[j][0] += v2 * v2;
                ps[j][1] += v3; pq[j][1] += v3 * v3;
            }
        }
    }
    // reduce over g-lanes (xor 4,8,16), then lanes 0-3 hold per-column sums
    #pragma unroll
    for (int j = 0; j < 4; j++)
        #pragma unroll
        for (int t2 = 0; t2 < 2; t2++) {
            float s = ps[j][t2], q = pq[j][t2];
            s += __shfl_xor_sync(0xFFFFFFFFu, s, 4);
            q += __shfl_xor_sync(0xFFFFFFFFu, q, 4);
            s += __shfl_xor_sync(0xFFFFFFFFu, s, 8);
            q += __shfl_xor_sync(0xFFFFFFFFu, q, 8);
            s += __shfl_xor_sync(0xFFFFFFFFu, s, 16);
            q += __shfl_xor_sync(0xFFFFFFFFu, q, 16);
            if (lane < 4) {
                int col = bn0 + ncol + j * 8 + 2 * tg + t2;
                atomicAdd(gsum + col, s);
                atomicAdd(gsq  + col, q);
            }
        }
}

// ---------------- BN stats -> affine ----------------
__global__ void k_finalize(const float* __restrict__ gsum, const float* __restrict__ gsq,
                           const float* __restrict__ gamma, const float* __restrict__ beta,
                           float* __restrict__ aff, int ncols) {
    int c = threadIdx.x;
    if (c >= ncols) return;
    const float invn = 1.0f / (float)NNODES;
    float mu  = gsum[c] * invn;
    float var = fmaxf(gsq[c] * invn - mu * mu, 0.f);
    float sc  = rsqrtf(var + 1e-5f) * gamma[c];
    aff[c]         = sc;
    aff[ncols + c] = beta[c] - mu * sc;
}

// ---------------- apply BN2 (+optional ReLU): h = bn(z2); z = h ----------------
__global__ void k_bnapply(int relu) {
    int i = blockIdx.x * blockDim.x + threadIdx.x;
    if (i >= NNODES * 32) return;
    int n = i >> 5, c = (i & 31) * 4;
    float4 v  = *(const float4*)(g_z + (size_t)n * DIM + c);
    float4 sc = *(const float4*)(g_aff2 + c);
    float4 sh = *(const float4*)(g_aff2 + DIM + c);
    v.x = fmaf(v.x, sc.x, sh.x);
    v.y = fmaf(v.y, sc.y, sh.y);
    v.z = fmaf(v.z, sc.z, sh.z);
    v.w = fmaf(v.w, sc.w, sh.w);
    if (relu) {
        v.x = fmaxf(v.x, 0.f); v.y = fmaxf(v.y, 0.f);
        v.z = fmaxf(v.z, 0.f); v.w = fmaxf(v.w, 0.f);
    }
    *(float4*)(g_h + (size_t)n * DIM + c) = v;
    *(float4*)(g_z + (size_t)n * DIM + c) = v;
}

__global__ void k_zero_out(float* __restrict__ out) {
    int i = blockIdx.x * blockDim.x + threadIdx.x;
    if (i < NGRAPH * DIM) out[i] = 0.f;
}

__global__ void k_pool(const int* __restrict__ batch, float* __restrict__ out) {
    int i = blockIdx.x * blockDim.x + threadIdx.x;
    if (i >= NNODES * 32) return;
    int n = i >> 5, c = (i & 31) * 4;
    float4 v = *(const float4*)(g_h + (size_t)n * DIM + c);
    *(float4*)(out + (size_t)NGRAPH * DIM + (size_t)n * DIM + c) = v;
    int b = __ldg(batch + n);
    red_add_v4(out + (size_t)b * DIM + c, v);
}

// ---------------- launch ----------------
extern "C" void kernel_launch(void* const* d_in, const int* in_sizes, int n_in,
                              void* d_out, int out_size) {
    const int*   batch    = (const int*)  d_in[0];
    const int*   x        = (const int*)  d_in[1];
    const int*   eidx     = (const int*)  d_in[2];
    const int*   eattr    = (const int*)  d_in[3];
    const float* atom_emb = (const float*)d_in[4];
    const float* bond_emb = (const float*)d_in[5];
    const float* W1       = (const float*)d_in[6];
    const float* b1       = (const float*)d_in[7];
    const float* g1       = (const float*)d_in[8];
    const float* be1      = (const float*)d_in[9];
    const float* W2       = (const float*)d_in[10];
    const float* b2       = (const float*)d_in[11];
    const float* gbn      = (const float*)d_in[12];
    const float* bbn      = (const float*)d_in[13];
    float* out = (float*)d_out;

    float *p_z, *p_z1, *p_sum1, *p_sq1, *p_aff1, *p_sum2, *p_sq2, *p_aff2;
    float *p_w1h, *p_w1l, *p_w2h, *p_w2l;
    cudaGetSymbolAddress((void**)&p_z,    g_z);
    cudaGetSymbolAddress((void**)&p_z1,   g_z1);
    cudaGetSymbolAddress((void**)&p_sum1, g_sum1);
    cudaGetSymbolAddress((void**)&p_sq1,  g_sq1);
    cudaGetSymbolAddress((void**)&p_aff1, g_aff1);
    cudaGetSymbolAddress((void**)&p_sum2, g_sum2);
    cudaGetSymbolAddress((void**)&p_sq2,  g_sq2);
    cudaGetSymbolAddress((void**)&p_aff2, g_aff2);
    cudaGetSymbolAddress((void**)&p_w1h,  g_w1h);
    cudaGetSymbolAddress((void**)&p_w1l,  g_w1l);
    cudaGetSymbolAddress((void**)&p_w2h,  g_w2h);
    cudaGetSymbolAddress((void**)&p_w2l,  g_w2l);

    cudaFuncSetAttribute(k_gemm_t<DIM,  DIM2, false>,
                         cudaFuncAttributeMaxDynamicSharedMemorySize, SMEM_BYTES);
    cudaFuncSetAttribute(k_gemm_t<DIM2, DIM,  true>,
                         cudaFuncAttributeMaxDynamicSharedMemorySize, SMEM_BYTES);

    const int* src = eidx;
    const int* dst = eidx + NEDGE;
    const int ELEM_GRID = (NNODES * 32 + 255) / 256;
    const int PREP_TOT  = 2 * NLAYERS * DIM * DIM2;

    k_init<<<ELEM_GRID, 256>>>(x, atom_emb);
    k_prep<<<(PREP_TOT + 255) / 256, 256>>>(W1, W2);

    for (int i = 0; i < NLAYERS; i++) {
        k_zero_stats<<<1, 256>>>();
        k_scatter<<<(NEDGE + 7) / 8, 256>>>(src, dst, eattr, bond_emb);
        k_gemm_t<DIM, DIM2, false><<<dim3(NPAD / 128, 2), 256, SMEM_BYTES>>>(
            p_z, p_w1h + (size_t)i * DIM2 * DIM, p_w1l + (size_t)i * DIM2 * DIM,
            b1 + (size_t)i * DIM2, nullptr, p_z1, p_sum1, p_sq1);
        k_finalize<<<1, DIM2>>>(p_sum1, p_sq1, g1 + (size_t)i * DIM2, be1 + (size_t)i * DIM2,
                                p_aff1, DIM2);
        k_gemm_t<DIM2, DIM, true><<<dim3(NPAD / 128, 1), 256, SMEM_BYTES>>>(
            p_z1, p_w2h + (size_t)i * DIM * DIM2, p_w2l + (size_t)i * DIM * DIM2,
            b2 + (size_t)i * DIM, p_aff1, p_z, p_sum2, p_sq2);
        k_finalize<<<1, DIM>>>(p_sum2, p_sq2, gbn + (size_t)i * DIM, bbn + (size_t)i * DIM,
                               p_aff2, DIM);
        k_bnapply<<<ELEM_GRID, 256>>>(i < NLAYERS - 1 ? 1 : 0);
    }

    k_zero_out<<<(NGRAPH * DIM + 255) / 256, 256>>>(out);
    k_pool<<<ELEM_GRID, 256>>>(batch, out);
}

// round 7
// speedup vs baseline: 1.1969x; 1.1969x over previous
#include <cuda_runtime.h>
#include <cstdint>

#define NNODES  50000
#define NPAD    50048      // 391 * 128
#define NEDGE   500000
#define DIM     128
#define DIM2    256
#define NLAYERS 5
#define NGRAPH  128

// ---------------- scratch (static device globals; zero-initialized) ----------------
__device__ float g_h [(size_t)NPAD * DIM];
__device__ float g_z [(size_t)NPAD * DIM];
__device__ float g_z1[(size_t)NPAD * DIM2];
__device__ float g_sum1[DIM2], g_sq1[DIM2], g_aff1[2 * DIM2];
__device__ float g_sum2[DIM ], g_sq2[DIM ], g_aff2[2 * DIM ];

// ---------------- PTX helpers (baseline features only) ----------------
__device__ __forceinline__ void red_add_v4(float* p, float4 v) {
    asm volatile("red.global.add.v4.f32 [%0], {%1, %2, %3, %4};"
                 :: "l"(p), "f"(v.x), "f"(v.y), "f"(v.z), "f"(v.w) : "memory");
}
__device__ __forceinline__ unsigned long long pack2(float x) {
    unsigned long long r;
    asm("mov.b64 %0, {%1, %1};" : "=l"(r) : "r"(__float_as_uint(x)));
    return r;
}
__device__ __forceinline__ void fma2(unsigned long long& d,
                                     unsigned long long a, unsigned long long b) {
    asm("fma.rn.f32x2 %0, %1, %2, %0;" : "+l"(d) : "l"(a), "l"(b));
}

// ---------------- layer-0 init: h = atom_emb[x]; z = h ----------------
__global__ void k_init(const int* __restrict__ x, const float* __restrict__ atom_emb) {
    int i = blockIdx.x * blockDim.x + threadIdx.x;
    if (i >= NNODES * 32) return;
    int n = i >> 5, c = (i & 31) * 4;
    int a = __ldg(x + n);
    float4 v = *(const float4*)(atom_emb + (size_t)a * DIM + c);
    *(float4*)(g_h + (size_t)n * DIM + c) = v;
    *(float4*)(g_z + (size_t)n * DIM + c) = v;
}

// ---------------- message passing: z[dst] += relu(h[src] + bond_emb[attr]) ----------------
__global__ void k_scatter(const int* __restrict__ src, const int* __restrict__ dst,
                          const int* __restrict__ eattr, const float* __restrict__ bond_emb) {
    int e = blockIdx.x * 8 + (threadIdx.x >> 5);
    if (e >= NEDGE) return;
    int lane = threadIdx.x & 31;
    int s = __ldg(src + e), d = __ldg(dst + e), a = __ldg(eattr + e);
    float4 hv = *(const float4*)(g_h + (size_t)s * DIM + lane * 4);
    float4 ev = *(const float4*)(bond_emb + (size_t)a * DIM + lane * 4);
    float4 m;
    m.x = fmaxf(hv.x + ev.x, 0.f);
    m.y = fmaxf(hv.y + ev.y, 0.f);
    m.z = fmaxf(hv.z + ev.z, 0.f);
    m.w = fmaxf(hv.w + ev.w, 0.f);
    red_add_v4(g_z + (size_t)d * DIM + lane * 4, m);
}

__global__ void k_zero_stats() {
    int t = threadIdx.x;
    if (t < DIM2) { g_sum1[t] = 0.f; g_sq1[t] = 0.f; }
    if (t < DIM)  { g_sum2[t] = 0.f; g_sq2[t] = 0.f; }
}

// ---------------- SGEMM via packed FFMA2: C[NPAD x NC] = A[NPAD x K] @ Bw[K x NC] + bias ----
// BM=128, BN=64, BK=16, 256 threads, 8x4 microtile (n-packed f32x2 accumulators),
// double-buffered smem, register prefetch. ~85 regs -> 3 CTAs/SM.
// If AFF: A transformed a' = relu(a*scale[k] + shift[k]) on smem staging.
// Epilogue: bias add, store, per-column sum/sumsq (rows < NNODES) for next BN.
// smem floats: As[2][16][132] @0 (4224) | Bs[2][16][64] @4224 (2048) | saff @6272 (512)
template<int K, int NC, bool AFF>
__global__ void __launch_bounds__(256, 3)
k_gemm(const float* __restrict__ A, const float* __restrict__ Bw,
       const float* __restrict__ bias, const float* __restrict__ aff,
       float* __restrict__ C, float* __restrict__ gsum, float* __restrict__ gsq) {
    __shared__ float smem[4224 + 2048 + 512];
    float* saff = smem + 6272;

    const int tid = threadIdx.x;
    const int tx  = tid & 15, ty = tid >> 4;          // n: tx*4 (4 cols), m: ty*8 (8 rows)
    const int bm0 = blockIdx.x * 128, bn0 = blockIdx.y * 64;

    const int a_row = tid >> 2;                       // 0..63 (+64)
    const int a_c4  = (tid & 3) * 4;
    const int b_row = tid >> 4;                       // 0..15
    const int b_c   = (tid & 15) * 4;

    if (AFF) {
        for (int t = tid; t < 2 * K; t += 256) saff[t] = aff[t];
        __syncthreads();
    }

    unsigned long long acc2[8][2];                    // [m][n-pair]; lo = even col
    #pragma unroll
    for (int m = 0; m < 8; m++) { acc2[m][0] = 0ULL; acc2[m][1] = 0ULL; }

    const float* Abase = A  + (size_t)(bm0 + a_row) * K + a_c4;
    const float* Bbase = Bw + (size_t)b_row * NC + bn0 + b_c;

    float4 pa0, pa1, pb0;
    pa0 = *(const float4*)(Abase);
    pa1 = *(const float4*)(Abase + (size_t)64 * K);
    pb0 = *(const float4*)(Bbase);

    #pragma unroll 1
    for (int k0 = 0; k0 < K; k0 += 16) {
        const bool nxt = (k0 + 16) < K;
        {
            const int buf = (k0 >> 4) & 1;
            if (AFF) {
                const float* sc = saff + k0 + a_c4;
                const float* sh = sc + K;
                pa0.x = fmaxf(fmaf(pa0.x, sc[0], sh[0]), 0.f);
                pa0.y = fmaxf(fmaf(pa0.y, sc[1], sh[1]), 0.f);
                pa0.z = fmaxf(fmaf(pa0.z, sc[2], sh[2]), 0.f);
                pa0.w = fmaxf(fmaf(pa0.w, sc[3], sh[3]), 0.f);
                pa1.x = fmaxf(fmaf(pa1.x, sc[0], sh[0]), 0.f);
                pa1.y = fmaxf(fmaf(pa1.y, sc[1], sh[1]), 0.f);
                pa1.z = fmaxf(fmaf(pa1.z, sc[2], sh[2]), 0.f);
                pa1.w = fmaxf(fmaf(pa1.w, sc[3], sh[3]), 0.f);
            }
            float* as = smem + buf * 2112;
            as[(a_c4 + 0) * 132 + a_row] = pa0.x;
            as[(a_c4 + 1) * 132 + a_row] = pa0.y;
            as[(a_c4 + 2) * 132 + a_row] = pa0.z;
            as[(a_c4 + 3) * 132 + a_row] = pa0.w;
            as[(a_c4 + 0) * 132 + a_row + 64] = pa1.x;
            as[(a_c4 + 1) * 132 + a_row + 64] = pa1.y;
            as[(a_c4 + 2) * 132 + a_row + 64] = pa1.z;
            as[(a_c4 + 3) * 132 + a_row + 64] = pa1.w;
            float* bs = smem + 4224 + buf * 1024;
            *(float4*)(bs + b_row * 64 + b_c) = pb0;
        }
        __syncthreads();

        if (nxt) {
            pa0 = *(const float4*)(Abase + k0 + 16);
            pa1 = *(const float4*)(Abase + (size_t)64 * K + k0 + 16);
            pb0 = *(const float4*)(Bbase + (size_t)(k0 + 16) * NC);
        }

        {
            const int buf = (k0 >> 4) & 1;
            const float* as = smem + buf * 2112;
            const float* bs = smem + 4224 + buf * 1024;
            #pragma unroll
            for (int kk = 0; kk < 16; kk++) {
                float ar[8];
                unsigned long long brp[2];
                *(float4*)&ar[0]  = *(const float4*)(as + kk * 132 + ty * 8);
                *(float4*)&ar[4]  = *(const float4*)(as + kk * 132 + ty * 8 + 4);
                *(float4*)&brp[0] = *(const float4*)(bs + kk * 64 + tx * 4);
                #pragma unroll
                for (int m = 0; m < 8; m++) {
                    unsigned long long ap = pack2(ar[m]);
                    fma2(acc2[m][0], ap, brp[0]);
                    fma2(acc2[m][1], ap, brp[1]);
                }
            }
        }
    }

    // epilogue: bias add, store, masked per-column stats
    float4 bvq = *(const float4*)(bias + bn0 + tx * 4);
    float psum[4] = {0.f, 0.f, 0.f, 0.f}, psq[4] = {0.f, 0.f, 0.f, 0.f};
    #pragma unroll
    for (int m = 0; m < 8; m++) {
        int row = bm0 + ty * 8 + m;
        const float* accf = (const float*)&acc2[m][0];
        float4 v;
        v.x = accf[0] + bvq.x; v.y = accf[1] + bvq.y;
        v.z = accf[2] + bvq.z; v.w = accf[3] + bvq.w;
        *(float4*)(C + (size_t)row * NC + bn0 + tx * 4) = v;
        if (row < NNODES) {
            psum[0] += v.x; psq[0] += v.x * v.x;
            psum[1] += v.y; psq[1] += v.y * v.y;
            psum[2] += v.z; psq[2] += v.z * v.z;
            psum[3] += v.w; psq[3] += v.w * v.w;
        }
    }

    __syncthreads();
    float* ssum = smem;                    // [16][64]
    float* ssq  = smem + 1024;             // [16][64]
    #pragma unroll
    for (int n = 0; n < 4; n++) {
        ssum[ty * 64 + tx * 4 + n] = psum[n];
        ssq [ty * 64 + tx * 4 + n] = psq[n];
    }
    __syncthreads();
    if (tid < 64) {
        float s = 0.f, q = 0.f;
        #pragma unroll
        for (int i = 0; i < 16; i++) { s += ssum[i * 64 + tid]; q += ssq[i * 64 + tid]; }
        atomicAdd(gsum + bn0 + tid, s);
        atomicAdd(gsq  + bn0 + tid, q);
    }
}

// ---------------- BN stats -> affine ----------------
__global__ void k_finalize(const float* __restrict__ gsum, const float* __restrict__ gsq,
                           const float* __restrict__ gamma, const float* __restrict__ beta,
                           float* __restrict__ aff, int ncols) {
    int c = threadIdx.x;
    if (c >= ncols) return;
    const float invn = 1.0f / (float)NNODES;
    float mu  = gsum[c] * invn;
    float var = fmaxf(gsq[c] * invn - mu * mu, 0.f);
    float sc  = rsqrtf(var + 1e-5f) * gamma[c];
    aff[c]         = sc;
    aff[ncols + c] = beta[c] - mu * sc;
}

// ---------------- apply BN2 (+optional ReLU): h = bn(z2); z = h ----------------
__global__ void k_bnapply(int relu) {
    int i = blockIdx.x * blockDim.x + threadIdx.x;
    if (i >= NNODES * 32) return;
    int n = i >> 5, c = (i & 31) * 4;
    float4 v  = *(const float4*)(g_z + (size_t)n * DIM + c);
    float4 sc = *(const float4*)(g_aff2 + c);
    float4 sh = *(const float4*)(g_aff2 + DIM + c);
    v.x = fmaf(v.x, sc.x, sh.x);
    v.y = fmaf(v.y, sc.y, sh.y);
    v.z = fmaf(v.z, sc.z, sh.z);
    v.w = fmaf(v.w, sc.w, sh.w);
    if (relu) {
        v.x = fmaxf(v.x, 0.f); v.y = fmaxf(v.y, 0.f);
        v.z = fmaxf(v.z, 0.f); v.w = fmaxf(v.w, 0.f);
    }
    *(float4*)(g_h + (size_t)n * DIM + c) = v;
    *(float4*)(g_z + (size_t)n * DIM + c) = v;
}

__global__ void k_zero_out(float* __restrict__ out) {
    int i = blockIdx.x * blockDim.x + threadIdx.x;
    if (i < NGRAPH * DIM) out[i] = 0.f;
}

__global__ void k_pool(const int* __restrict__ batch, float* __restrict__ out) {
    int i = blockIdx.x * blockDim.x + threadIdx.x;
    if (i >= NNODES * 32) return;
    int n = i >> 5, c = (i & 31) * 4;
    float4 v = *(const float4*)(g_h + (size_t)n * DIM + c);
    *(float4*)(out + (size_t)NGRAPH * DIM + (size_t)n * DIM + c) = v;
    int b = __ldg(batch + n);
    red_add_v4(out + (size_t)b * DIM + c, v);
}

// ---------------- launch ----------------
extern "C" void kernel_launch(void* const* d_in, const int* in_sizes, int n_in,
                              void* d_out, int out_size) {
    const int*   batch    = (const int*)  d_in[0];
    const int*   x        = (const int*)  d_in[1];
    const int*   eidx     = (const int*)  d_in[2];
    const int*   eattr    = (const int*)  d_in[3];
    const float* atom_emb = (const float*)d_in[4];
    const float* bond_emb = (const float*)d_in[5];
    const float* W1       = (const float*)d_in[6];
    const float* b1       = (const float*)d_in[7];
    const float* g1       = (const float*)d_in[8];
    const float* be1      = (const float*)d_in[9];
    const float* W2       = (const float*)d_in[10];
    const float* b2       = (const float*)d_in[11];
    const float* gbn      = (const float*)d_in[12];
    const float* bbn      = (const float*)d_in[13];
    float* out = (float*)d_out;

    float *p_z, *p_z1, *p_sum1, *p_sq1, *p_aff1, *p_sum2, *p_sq2, *p_aff2;
    cudaGetSymbolAddress((void**)&p_z,    g_z);
    cudaGetSymbolAddress((void**)&p_z1,   g_z1);
    cudaGetSymbolAddress((void**)&p_sum1, g_sum1);
    cudaGetSymbolAddress((void**)&p_sq1,  g_sq1);
    cudaGetSymbolAddress((void**)&p_aff1, g_aff1);
    cudaGetSymbolAddress((void**)&p_sum2, g_sum2);
    cudaGetSymbolAddress((void**)&p_sq2,  g_sq2);
    cudaGetSymbolAddress((void**)&p_aff2, g_aff2);

    const int* src = eidx;
    const int* dst = eidx + NEDGE;
    const int ELEM_GRID = (NNODES * 32 + 255) / 256;

    k_init<<<ELEM_GRID, 256>>>(x, atom_emb);

    for (int i = 0; i < NLAYERS; i++) {
        k_zero_stats<<<1, 256>>>();
        k_scatter<<<(NEDGE + 7) / 8, 256>>>(src, dst, eattr, bond_emb);
        k_gemm<DIM, DIM2, false><<<dim3(NPAD / 128, DIM2 / 64), 256>>>(
            p_z, W1 + (size_t)i * DIM * DIM2, b1 + (size_t)i * DIM2, nullptr,
            p_z1, p_sum1, p_sq1);
        k_finalize<<<1, DIM2>>>(p_sum1, p_sq1, g1 + (size_t)i * DIM2, be1 + (size_t)i * DIM2,
                                p_aff1, DIM2);
        k_gemm<DIM2, DIM, true><<<dim3(NPAD / 128, DIM / 64), 256>>>(
            p_z1, W2 + (size_t)i * DIM2 * DIM, b2 + (size_t)i * DIM, p_aff1,
            p_z, p_sum2, p_sq2);
        k_finalize<<<1, DIM>>>(p_sum2, p_sq2, gbn + (size_t)i * DIM, bbn + (size_t)i * DIM,
                               p_aff2, DIM);
        k_bnapply<<<ELEM_GRID, 256>>>(i < NLAYERS - 1 ? 1 : 0);
    }

    k_zero_out<<<(NGRAPH * DIM + 255) / 256, 256>>>(out);
    k_pool<<<ELEM_GRID, 256>>>(batch, out);
}

// round 8
// speedup vs baseline: 1.2346x; 1.0315x over previous
#include <cuda_runtime.h>
#include <cstdint>

#define NNODES  50000
#define NPAD    50048      // 391 * 128
#define NEDGE   500000
#define DIM     128
#define DIM2    256
#define NLAYERS 5
#define NGRAPH  128

// ---------------- scratch (static device globals; zero-initialized) ----------------
__device__ float g_h [(size_t)NPAD * DIM];
__device__ float g_z [(size_t)NPAD * DIM];
__device__ float g_z1[(size_t)NPAD * DIM2];
__device__ float g_sum1[DIM2], g_sq1[DIM2], g_aff1[2 * DIM2];
__device__ float g_sum2[DIM ], g_sq2[DIM ], g_aff2[2 * DIM ];

// ---------------- PTX helpers (baseline features only) ----------------
__device__ __forceinline__ void red_add_v4(float* p, float4 v) {
    asm volatile("red.global.add.v4.f32 [%0], {%1, %2, %3, %4};"
                 :: "l"(p), "f"(v.x), "f"(v.y), "f"(v.z), "f"(v.w) : "memory");
}
__device__ __forceinline__ unsigned long long pack2(float x) {
    unsigned long long r;
    asm("mov.b64 %0, {%1, %1};" : "=l"(r) : "r"(__float_as_uint(x)));
    return r;
}
__device__ __forceinline__ void fma2(unsigned long long& d,
                                     unsigned long long a, unsigned long long b) {
    asm("fma.rn.f32x2 %0, %1, %2, %0;" : "+l"(d) : "l"(a), "l"(b));
}

// ---------------- layer-0 init: h = atom_emb[x]; z = h ----------------
__global__ void k_init(const int* __restrict__ x, const float* __restrict__ atom_emb) {
    int i = blockIdx.x * blockDim.x + threadIdx.x;
    if (i >= NNODES * 32) return;
    int n = i >> 5, c = (i & 31) * 4;
    int a = __ldg(x + n);
    float4 v = *(const float4*)(atom_emb + (size_t)a * DIM + c);
    *(float4*)(g_h + (size_t)n * DIM + c) = v;
    *(float4*)(g_z + (size_t)n * DIM + c) = v;
}

// ---------------- message passing: z[dst] += relu(h[src] + bond_emb[attr]) ----------------
__global__ void k_scatter(const int* __restrict__ src, const int* __restrict__ dst,
                          const int* __restrict__ eattr, const float* __restrict__ bond_emb) {
    int e = blockIdx.x * 8 + (threadIdx.x >> 5);
    if (e >= NEDGE) return;
    int lane = threadIdx.x & 31;
    int s = __ldg(src + e), d = __ldg(dst + e), a = __ldg(eattr + e);
    float4 hv = *(const float4*)(g_h + (size_t)s * DIM + lane * 4);
    float4 ev = *(const float4*)(bond_emb + (size_t)a * DIM + lane * 4);
    float4 m;
    m.x = fmaxf(hv.x + ev.x, 0.f);
    m.y = fmaxf(hv.y + ev.y, 0.f);
    m.z = fmaxf(hv.z + ev.z, 0.f);
    m.w = fmaxf(hv.w + ev.w, 0.f);
    red_add_v4(g_z + (size_t)d * DIM + lane * 4, m);
}

// ---------------- SGEMM via packed FFMA2 (m-paired accumulators) ----------------
// C[NPAD x NC] = A[NPAD x K] @ Bw[K x NC] + bias
// BM=128, BN=64, BK=16, 256 threads, 8x4 microtile.
// Accumulators acc2[mp][n]: u64 f32x2 pair over adjacent M rows (free from float4 LDS
// of transposed As); B values broadcast-packed (4 pack2/kk instead of 8).
// If AFF: A transformed a' = relu(a*scale[k] + shift[k]) on smem staging.
// Epilogue: bias add, store, per-column sum/sumsq (rows < NNODES) for next BN.
// smem floats: As[2][16][132] @0 (4224) | Bs[2][16][64] @4224 (2048) | saff @6272 (512)
template<int K, int NC, bool AFF>
__global__ void __launch_bounds__(256, 3)
k_gemm(const float* __restrict__ A, const float* __restrict__ Bw,
       const float* __restrict__ bias, const float* __restrict__ aff,
       float* __restrict__ C, float* __restrict__ gsum, float* __restrict__ gsq) {
    __shared__ float smem[4224 + 2048 + 512];
    float* saff = smem + 6272;

    const int tid = threadIdx.x;
    const int tx  = tid & 15, ty = tid >> 4;          // n: tx*4 (4 cols), m: ty*8 (8 rows)
    const int bm0 = blockIdx.x * 128, bn0 = blockIdx.y * 64;

    const int a_row = tid >> 2;                       // 0..63 (+64)
    const int a_c4  = (tid & 3) * 4;
    const int b_row = tid >> 4;                       // 0..15
    const int b_c   = (tid & 15) * 4;

    if (AFF) {
        for (int t = tid; t < 2 * K; t += 256) saff[t] = aff[t];
        __syncthreads();
    }

    unsigned long long acc2[4][4];    // [m-pair][n]; lo = even row of pair
    #pragma unroll
    for (int mp = 0; mp < 4; mp++)
        #pragma unroll
        for (int n = 0; n < 4; n++) acc2[mp][n] = 0ULL;

    const float* Abase = A  + (size_t)(bm0 + a_row) * K + a_c4;
    const float* Bbase = Bw + (size_t)b_row * NC + bn0 + b_c;

    float4 pa0, pa1, pb0;
    pa0 = *(const float4*)(Abase);
    pa1 = *(const float4*)(Abase + (size_t)64 * K);
    pb0 = *(const float4*)(Bbase);

    #pragma unroll 1
    for (int k0 = 0; k0 < K; k0 += 16) {
        const bool nxt = (k0 + 16) < K;
        {
            const int buf = (k0 >> 4) & 1;
            if (AFF) {
                const float* sc = saff + k0 + a_c4;
                const float* sh = sc + K;
                pa0.x = fmaxf(fmaf(pa0.x, sc[0], sh[0]), 0.f);
                pa0.y = fmaxf(fmaf(pa0.y, sc[1], sh[1]), 0.f);
                pa0.z = fmaxf(fmaf(pa0.z, sc[2], sh[2]), 0.f);
                pa0.w = fmaxf(fmaf(pa0.w, sc[3], sh[3]), 0.f);
                pa1.x = fmaxf(fmaf(pa1.x, sc[0], sh[0]), 0.f);
                pa1.y = fmaxf(fmaf(pa1.y, sc[1], sh[1]), 0.f);
                pa1.z = fmaxf(fmaf(pa1.z, sc[2], sh[2]), 0.f);
                pa1.w = fmaxf(fmaf(pa1.w, sc[3], sh[3]), 0.f);
            }
            float* as = smem + buf * 2112;
            as[(a_c4 + 0) * 132 + a_row] = pa0.x;
            as[(a_c4 + 1) * 132 + a_row] = pa0.y;
            as[(a_c4 + 2) * 132 + a_row] = pa0.z;
            as[(a_c4 + 3) * 132 + a_row] = pa0.w;
            as[(a_c4 + 0) * 132 + a_row + 64] = pa1.x;
            as[(a_c4 + 1) * 132 + a_row + 64] = pa1.y;
            as[(a_c4 + 2) * 132 + a_row + 64] = pa1.z;
            as[(a_c4 + 3) * 132 + a_row + 64] = pa1.w;
            float* bs = smem + 4224 + buf * 1024;
            *(float4*)(bs + b_row * 64 + b_c) = pb0;
        }
        __syncthreads();

        if (nxt) {
            pa0 = *(const float4*)(Abase + k0 + 16);
            pa1 = *(const float4*)(Abase + (size_t)64 * K + k0 + 16);
            pb0 = *(const float4*)(Bbase + (size_t)(k0 + 16) * NC);
        }

        {
            const int buf = (k0 >> 4) & 1;
            const float* as = smem + buf * 2112;
            const float* bs = smem + 4224 + buf * 1024;
            #pragma unroll
            for (int kk = 0; kk < 16; kk++) {
                unsigned long long am[4];            // m-pairs, free from float4 loads
                float br[4];
                *(float4*)&am[0] = *(const float4*)(as + kk * 132 + ty * 8);
                *(float4*)&am[2] = *(const float4*)(as + kk * 132 + ty * 8 + 4);
                *(float4*)&br[0] = *(const float4*)(bs + kk * 64 + tx * 4);
                unsigned long long bp0 = pack2(br[0]);
                unsigned long long bp1 = pack2(br[1]);
                unsigned long long bp2 = pack2(br[2]);
                unsigned long long bp3 = pack2(br[3]);
                #pragma unroll
                for (int mp = 0; mp < 4; mp++) {
                    fma2(acc2[mp][0], am[mp], bp0);
                    fma2(acc2[mp][1], am[mp], bp1);
                    fma2(acc2[mp][2], am[mp], bp2);
                    fma2(acc2[mp][3], am[mp], bp3);
                }
            }
        }
    }

    // epilogue: bias add, store, masked per-column stats
    float4 bvq = *(const float4*)(bias + bn0 + tx * 4);
    float psum[4] = {0.f, 0.f, 0.f, 0.f}, psq[4] = {0.f, 0.f, 0.f, 0.f};
    #pragma unroll
    for (int m = 0; m < 8; m++) {
        const int mp = m >> 1, par = m & 1;
        int row = bm0 + ty * 8 + m;
        float4 v;
        v.x = ((const float*)&acc2[mp][0])[par] + bvq.x;
        v.y = ((const float*)&acc2[mp][1])[par] + bvq.y;
        v.z = ((const float*)&acc2[mp][2])[par] + bvq.z;
        v.w = ((const float*)&acc2[mp][3])[par] + bvq.w;
        *(float4*)(C + (size_t)row * NC + bn0 + tx * 4) = v;
        if (row < NNODES) {
            psum[0] += v.x; psq[0] += v.x * v.x;
            psum[1] += v.y; psq[1] += v.y * v.y;
            psum[2] += v.z; psq[2] += v.z * v.z;
            psum[3] += v.w; psq[3] += v.w * v.w;
        }
    }

    __syncthreads();
    float* ssum = smem;                    // [16][64]
    float* ssq  = smem + 1024;             // [16][64]
    #pragma unroll
    for (int n = 0; n < 4; n++) {
        ssum[ty * 64 + tx * 4 + n] = psum[n];
        ssq [ty * 64 + tx * 4 + n] = psq[n];
    }
    __syncthreads();
    if (tid < 64) {
        float s = 0.f, q = 0.f;
        #pragma unroll
        for (int i = 0; i < 16; i++) { s += ssum[i * 64 + tid]; q += ssq[i * 64 + tid]; }
        atomicAdd(gsum + bn0 + tid, s);
        atomicAdd(gsq  + bn0 + tid, q);
    }
}

// ---------------- BN stats -> affine; also re-zero stats for the next use ----------------
__global__ void k_finalize(float* __restrict__ gsum, float* __restrict__ gsq,
                           const float* __restrict__ gamma, const float* __restrict__ beta,
                           float* __restrict__ aff, int ncols) {
    int c = threadIdx.x;
    if (c >= ncols) return;
    const float invn = 1.0f / (float)NNODES;
    float mu  = gsum[c] * invn;
    float var = fmaxf(gsq[c] * invn - mu * mu, 0.f);
    float sc  = rsqrtf(var + 1e-5f) * gamma[c];
    aff[c]         = sc;
    aff[ncols + c] = beta[c] - mu * sc;
    gsum[c] = 0.f;                 // consumed -> reset (keeps replay invariant)
    gsq[c]  = 0.f;
}

// ---------------- apply BN2 (+optional ReLU): h = bn(z2); z = h ----------------
__global__ void k_bnapply(int relu) {
    int i = blockIdx.x * blockDim.x + threadIdx.x;
    if (i >= NNODES * 32) return;
    int n = i >> 5, c = (i & 31) * 4;
    float4 v  = *(const float4*)(g_z + (size_t)n * DIM + c);
    float4 sc = *(const float4*)(g_aff2 + c);
    float4 sh = *(const float4*)(g_aff2 + DIM + c);
    v.x = fmaf(v.x, sc.x, sh.x);
    v.y = fmaf(v.y, sc.y, sh.y);
    v.z = fmaf(v.z, sc.z, sh.z);
    v.w = fmaf(v.w, sc.w, sh.w);
    if (relu) {
        v.x = fmaxf(v.x, 0.f); v.y = fmaxf(v.y, 0.f);
        v.z = fmaxf(v.z, 0.f); v.w = fmaxf(v.w, 0.f);
    }
    *(float4*)(g_h + (size_t)n * DIM + c) = v;
    *(float4*)(g_z + (size_t)n * DIM + c) = v;
}

__global__ void k_zero_out(float* __restrict__ out) {
    int i = blockIdx.x * blockDim.x + threadIdx.x;
    if (i < NGRAPH * DIM) out[i] = 0.f;
}

__global__ void k_pool(const int* __restrict__ batch, float* __restrict__ out) {
    int i = blockIdx.x * blockDim.x + threadIdx.x;
    if (i >= NNODES * 32) return;
    int n = i >> 5, c = (i & 31) * 4;
    float4 v = *(const float4*)(g_h + (size_t)n * DIM + c);
    *(float4*)(out + (size_t)NGRAPH * DIM + (size_t)n * DIM + c) = v;
    int b = __ldg(batch + n);
    red_add_v4(out + (size_t)b * DIM + c, v);
}

// ---------------- launch ----------------
extern "C" void kernel_launch(void* const* d_in, const int* in_sizes, int n_in,
                              void* d_out, int out_size) {
    const int*   batch    = (const int*)  d_in[0];
    const int*   x        = (const int*)  d_in[1];
    const int*   eidx     = (const int*)  d_in[2];
    const int*   eattr    = (const int*)  d_in[3];
    const float* atom_emb = (const float*)d_in[4];
    const float* bond_emb = (const float*)d_in[5];
    const float* W1       = (const float*)d_in[6];
    const float* b1       = (const float*)d_in[7];
    const float* g1       = (const float*)d_in[8];
    const float* be1      = (const float*)d_in[9];
    const float* W2       = (const float*)d_in[10];
    const float* b2       = (const float*)d_in[11];
    const float* gbn      = (const float*)d_in[12];
    const float* bbn      = (const float*)d_in[13];
    float* out = (float*)d_out;

    float *p_z, *p_z1, *p_sum1, *p_sq1, *p_aff1, *p_sum2, *p_sq2, *p_aff2;
    cudaGetSymbolAddress((void**)&p_z,    g_z);
    cudaGetSymbolAddress((void**)&p_z1,   g_z1);
    cudaGetSymbolAddress((void**)&p_sum1, g_sum1);
    cudaGetSymbolAddress((void**)&p_sq1,  g_sq1);
    cudaGetSymbolAddress((void**)&p_aff1, g_aff1);
    cudaGetSymbolAddress((void**)&p_sum2, g_sum2);
    cudaGetSymbolAddress((void**)&p_sq2,  g_sq2);
    cudaGetSymbolAddress((void**)&p_aff2, g_aff2);

    const int* src = eidx;
    const int* dst = eidx + NEDGE;
    const int ELEM_GRID = (NNODES * 32 + 255) / 256;

    k_init<<<ELEM_GRID, 256>>>(x, atom_emb);

    for (int i = 0; i < NLAYERS; i++) {
        k_scatter<<<(NEDGE + 7) / 8, 256>>>(src, dst, eattr, bond_emb);
        k_gemm<DIM, DIM2, false><<<dim3(NPAD / 128, DIM2 / 64), 256>>>(
            p_z, W1 + (size_t)i * DIM * DIM2, b1 + (size_t)i * DIM2, nullptr,
            p_z1, p_sum1, p_sq1);
        k_finalize<<<1, DIM2>>>(p_sum1, p_sq1, g1 + (size_t)i * DIM2, be1 + (size_t)i * DIM2,
                                p_aff1, DIM2);
        k_gemm<DIM2, DIM, true><<<dim3(NPAD / 128, DIM / 64), 256>>>(
            p_z1, W2 + (size_t)i * DIM2 * DIM, b2 + (size_t)i * DIM, p_aff1,
            p_z, p_sum2, p_sq2);
        k_finalize<<<1, DIM>>>(p_sum2, p_sq2, gbn + (size_t)i * DIM, bbn + (size_t)i * DIM,
                               p_aff2, DIM);
        k_bnapply<<<ELEM_GRID, 256>>>(i < NLAYERS - 1 ? 1 : 0);
    }

    k_zero_out<<<(NGRAPH * DIM + 255) / 256, 256>>>(out);
    k_pool<<<ELEM_GRID, 256>>>(batch, out);
}

// round 9
// speedup vs baseline: 1.2747x; 1.0325x over previous
#include <cuda_runtime.h>
#include <cstdint>

#define NNODES  50000
#define NPAD    50048      // 391 * 128
#define NEDGE   500000
#define DIM     128
#define DIM2    256
#define NLAYERS 5
#define NGRAPH  128

// ---------------- scratch (static device globals; zero-initialized) ----------------
__device__ float g_h [(size_t)NPAD * DIM];
__device__ float g_z [(size_t)NPAD * DIM];
__device__ float g_z1[(size_t)NPAD * DIM2];
__device__ float g_sum1[DIM2], g_sq1[DIM2];
__device__ float g_sum2[DIM ], g_sq2[DIM ];
__device__ int   g_cnt1, g_cnt2;            // last-CTA arrival counters

// ---------------- PTX helpers (baseline features only) ----------------
__device__ __forceinline__ void red_add_v4(float* p, float4 v) {
    asm volatile("red.global.add.v4.f32 [%0], {%1, %2, %3, %4};"
                 :: "l"(p), "f"(v.x), "f"(v.y), "f"(v.z), "f"(v.w) : "memory");
}
__device__ __forceinline__ unsigned long long pack2(float x) {
    unsigned long long r;
    asm("mov.b64 %0, {%1, %1};" : "=l"(r) : "r"(__float_as_uint(x)));
    return r;
}
__device__ __forceinline__ void fma2(unsigned long long& d,
                                     unsigned long long a, unsigned long long b) {
    asm("fma.rn.f32x2 %0, %1, %2, %0;" : "+l"(d) : "l"(a), "l"(b));
}

// ---------------- layer-0 init: h = atom_emb[x]; z = h; zero xpool region ----------------
__global__ void k_init(const int* __restrict__ x, const float* __restrict__ atom_emb,
                       float* __restrict__ out) {
    int i = blockIdx.x * blockDim.x + threadIdx.x;
    if (i < NGRAPH * DIM) out[i] = 0.f;
    if (i >= NNODES * 32) return;
    int n = i >> 5, c = (i & 31) * 4;
    int a = __ldg(x + n);
    float4 v = *(const float4*)(atom_emb + (size_t)a * DIM + c);
    *(float4*)(g_h + (size_t)n * DIM + c) = v;
    *(float4*)(g_z + (size_t)n * DIM + c) = v;
}

// ---------------- message passing: z[dst] += relu(h[src] + bond_emb[attr]) ----------------
// 4 edges per warp for MLP; NEDGE % 32 == 0 so no bounds checks.
__global__ void k_scatter(const int* __restrict__ src, const int* __restrict__ dst,
                          const int* __restrict__ eattr, const float* __restrict__ bond_emb) {
    const int wid  = threadIdx.x >> 5;
    const int lane = threadIdx.x & 31;
    const int e0 = blockIdx.x * 32 + wid * 4;
    const int c4 = lane * 4;

    int s0 = __ldg(src + e0),     s1 = __ldg(src + e0 + 1);
    int s2 = __ldg(src + e0 + 2), s3 = __ldg(src + e0 + 3);
    int a0 = __ldg(eattr + e0),     a1 = __ldg(eattr + e0 + 1);
    int a2 = __ldg(eattr + e0 + 2), a3 = __ldg(eattr + e0 + 3);
    int d0 = __ldg(dst + e0),     d1 = __ldg(dst + e0 + 1);
    int d2 = __ldg(dst + e0 + 2), d3 = __ldg(dst + e0 + 3);

    float4 h0 = *(const float4*)(g_h + (size_t)s0 * DIM + c4);
    float4 h1 = *(const float4*)(g_h + (size_t)s1 * DIM + c4);
    float4 h2 = *(const float4*)(g_h + (size_t)s2 * DIM + c4);
    float4 h3 = *(const float4*)(g_h + (size_t)s3 * DIM + c4);
    float4 e0v = *(const float4*)(bond_emb + (size_t)a0 * DIM + c4);
    float4 e1v = *(const float4*)(bond_emb + (size_t)a1 * DIM + c4);
    float4 e2v = *(const float4*)(bond_emb + (size_t)a2 * DIM + c4);
    float4 e3v = *(const float4*)(bond_emb + (size_t)a3 * DIM + c4);

    float4 m;
    m.x = fmaxf(h0.x + e0v.x, 0.f); m.y = fmaxf(h0.y + e0v.y, 0.f);
    m.z = fmaxf(h0.z + e0v.z, 0.f); m.w = fmaxf(h0.w + e0v.w, 0.f);
    red_add_v4(g_z + (size_t)d0 * DIM + c4, m);
    m.x = fmaxf(h1.x + e1v.x, 0.f); m.y = fmaxf(h1.y + e1v.y, 0.f);
    m.z = fmaxf(h1.z + e1v.z, 0.f); m.w = fmaxf(h1.w + e1v.w, 0.f);
    red_add_v4(g_z + (size_t)d1 * DIM + c4, m);
    m.x = fmaxf(h2.x + e2v.x, 0.f); m.y = fmaxf(h2.y + e2v.y, 0.f);
    m.z = fmaxf(h2.z + e2v.z, 0.f); m.w = fmaxf(h2.w + e2v.w, 0.f);
    red_add_v4(g_z + (size_t)d2 * DIM + c4, m);
    m.x = fmaxf(h3.x + e3v.x, 0.f); m.y = fmaxf(h3.y + e3v.y, 0.f);
    m.z = fmaxf(h3.z + e3v.z, 0.f); m.w = fmaxf(h3.w + e3v.w, 0.f);
    red_add_v4(g_z + (size_t)d3 * DIM + c4, m);
}

// ---------------- SGEMM via packed FFMA2 (m-paired accumulators) ----------------
// C[NPAD x NC] = A[NPAD x K] @ Bw[K x NC] + bias
// BM=128, BN=64, BK=16, 256 threads, 8x4 microtile.
// If AFF: computes BN affine inline from stats (sumA/sqA + gammaA/betaA), applies
// a' = relu(a*sc[k] + sh[k]) on staging, and the LAST CTA to finish reading zeroes
// the stats arrays + resets the counter (replay invariant).
// Epilogue: bias add, store, per-column sum/sumsq (rows < NNODES) into gsum/gsq.
template<int K, int NC, bool AFF>
__global__ void __launch_bounds__(256, 3)
k_gemm(const float* __restrict__ A, const float* __restrict__ Bw,
       const float* __restrict__ bias,
       const float* __restrict__ sumA, const float* __restrict__ sqA,
       const float* __restrict__ gammaA, const float* __restrict__ betaA,
       int* __restrict__ cntA, int nCTA,
       float* __restrict__ C, float* __restrict__ gsum, float* __restrict__ gsq) {
    __shared__ float smem[4224 + 2048 + 512];
    __shared__ int s_last;
    float* saff = smem + 6272;

    const int tid = threadIdx.x;
    const int tx  = tid & 15, ty = tid >> 4;
    const int bm0 = blockIdx.x * 128, bn0 = blockIdx.y * 64;

    const int a_row = tid >> 2;
    const int a_c4  = (tid & 3) * 4;
    const int b_row = tid >> 4;
    const int b_c   = (tid & 15) * 4;

    if (AFF) {
        // inline finalize: thread t handles column t (K == 256 == blockDim)
        if (tid < K) {
            const float invn = 1.0f / (float)NNODES;
            float mu  = sumA[tid] * invn;
            float var = fmaxf(sqA[tid] * invn - mu * mu, 0.f);
            float sc  = rsqrtf(var + 1e-5f) * gammaA[tid];
            saff[tid]     = sc;
            saff[K + tid] = betaA[tid] - mu * sc;
        }
        __syncthreads();
        // last-CTA protocol: zero stats for next use
        if (tid == 0) {
            __threadfence();
            int old = atomicAdd(cntA, 1);
            s_last = (old == nCTA - 1);
        }
        __syncthreads();
        if (s_last) {
            if (tid < K) { ((float*)sumA)[tid] = 0.f; ((float*)sqA)[tid] = 0.f; }
            if (tid == 0) *cntA = 0;
        }
    }

    unsigned long long acc2[4][4];    // [m-pair][n]; lo = even row of pair
    #pragma unroll
    for (int mp = 0; mp < 4; mp++)
        #pragma unroll
        for (int n = 0; n < 4; n++) acc2[mp][n] = 0ULL;

    const float* Abase = A  + (size_t)(bm0 + a_row) * K + a_c4;
    const float* Bbase = Bw + (size_t)b_row * NC + bn0 + b_c;

    float4 pa0, pa1, pb0;
    pa0 = *(const float4*)(Abase);
    pa1 = *(const float4*)(Abase + (size_t)64 * K);
    pb0 = *(const float4*)(Bbase);

    #pragma unroll 1
    for (int k0 = 0; k0 < K; k0 += 16) {
        const bool nxt = (k0 + 16) < K;
        {
            const int buf = (k0 >> 4) & 1;
            if (AFF) {
                const float* sc = saff + k0 + a_c4;
                const float* sh = sc + K;
                pa0.x = fmaxf(fmaf(pa0.x, sc[0], sh[0]), 0.f);
                pa0.y = fmaxf(fmaf(pa0.y, sc[1], sh[1]), 0.f);
                pa0.z = fmaxf(fmaf(pa0.z, sc[2], sh[2]), 0.f);
                pa0.w = fmaxf(fmaf(pa0.w, sc[3], sh[3]), 0.f);
                pa1.x = fmaxf(fmaf(pa1.x, sc[0], sh[0]), 0.f);
                pa1.y = fmaxf(fmaf(pa1.y, sc[1], sh[1]), 0.f);
                pa1.z = fmaxf(fmaf(pa1.z, sc[2], sh[2]), 0.f);
                pa1.w = fmaxf(fmaf(pa1.w, sc[3], sh[3]), 0.f);
            }
            float* as = smem + buf * 2112;
            as[(a_c4 + 0) * 132 + a_row] = pa0.x;
            as[(a_c4 + 1) * 132 + a_row] = pa0.y;
            as[(a_c4 + 2) * 132 + a_row] = pa0.z;
            as[(a_c4 + 3) * 132 + a_row] = pa0.w;
            as[(a_c4 + 0) * 132 + a_row + 64] = pa1.x;
            as[(a_c4 + 1) * 132 + a_row + 64] = pa1.y;
            as[(a_c4 + 2) * 132 + a_row + 64] = pa1.z;
            as[(a_c4 + 3) * 132 + a_row + 64] = pa1.w;
            float* bs = smem + 4224 + buf * 1024;
            *(float4*)(bs + b_row * 64 + b_c) = pb0;
        }
        __syncthreads();

        if (nxt) {
            pa0 = *(const float4*)(Abase + k0 + 16);
            pa1 = *(const float4*)(Abase + (size_t)64 * K + k0 + 16);
            pb0 = *(const float4*)(Bbase + (size_t)(k0 + 16) * NC);
        }

        {
            const int buf = (k0 >> 4) & 1;
            const float* as = smem + buf * 2112;
            const float* bs = smem + 4224 + buf * 1024;
            #pragma unroll
            for (int kk = 0; kk < 16; kk++) {
                unsigned long long am[4];
                float br[4];
                *(float4*)&am[0] = *(const float4*)(as + kk * 132 + ty * 8);
                *(float4*)&am[2] = *(const float4*)(as + kk * 132 + ty * 8 + 4);
                *(float4*)&br[0] = *(const float4*)(bs + kk * 64 + tx * 4);
                unsigned long long bp0 = pack2(br[0]);
                unsigned long long bp1 = pack2(br[1]);
                unsigned long long bp2 = pack2(br[2]);
                unsigned long long bp3 = pack2(br[3]);
                #pragma unroll
                for (int mp = 0; mp < 4; mp++) {
                    fma2(acc2[mp][0], am[mp], bp0);
                    fma2(acc2[mp][1], am[mp], bp1);
                    fma2(acc2[mp][2], am[mp], bp2);
                    fma2(acc2[mp][3], am[mp], bp3);
                }
            }
        }
    }

    // epilogue: bias add, store, masked per-column stats
    float4 bvq = *(const float4*)(bias + bn0 + tx * 4);
    float psum[4] = {0.f, 0.f, 0.f, 0.f}, psq[4] = {0.f, 0.f, 0.f, 0.f};
    #pragma unroll
    for (int m = 0; m < 8; m++) {
        const int mp = m >> 1, par = m & 1;
        int row = bm0 + ty * 8 + m;
        float4 v;
        v.x = ((const float*)&acc2[mp][0])[par] + bvq.x;
        v.y = ((const float*)&acc2[mp][1])[par] + bvq.y;
        v.z = ((const float*)&acc2[mp][2])[par] + bvq.z;
        v.w = ((const float*)&acc2[mp][3])[par] + bvq.w;
        *(float4*)(C + (size_t)row * NC + bn0 + tx * 4) = v;
        if (row < NNODES) {
            psum[0] += v.x; psq[0] += v.x * v.x;
            psum[1] += v.y; psq[1] += v.y * v.y;
            psum[2] += v.z; psq[2] += v.z * v.z;
            psum[3] += v.w; psq[3] += v.w * v.w;
        }
    }

    __syncthreads();
    float* ssum = smem;                    // [16][64]
    float* ssq  = smem + 1024;             // [16][64]
    #pragma unroll
    for (int n = 0; n < 4; n++) {
        ssum[ty * 64 + tx * 4 + n] = psum[n];
        ssq [ty * 64 + tx * 4 + n] = psq[n];
    }
    __syncthreads();
    if (tid < 64) {
        float s = 0.f, q = 0.f;
        #pragma unroll
        for (int i = 0; i < 16; i++) { s += ssum[i * 64 + tid]; q += ssq[i * 64 + tid]; }
        atomicAdd(gsum + bn0 + tid, s);
        atomicAdd(gsq  + bn0 + tid, q);
    }
}

// ---------------- apply BN2 (+optional ReLU): h = bn(z2); z = h ----------------
// Computes aff2 inline from stats; last block zeroes stats + resets counter.
__global__ void k_bnapply(const float* __restrict__ gamma, const float* __restrict__ beta,
                          int relu, int nBLK) {
    __shared__ float saff[2 * DIM];
    __shared__ int s_last;
    int tid = threadIdx.x;
    if (tid < DIM) {
        const float invn = 1.0f / (float)NNODES;
        float mu  = g_sum2[tid] * invn;
        float var = fmaxf(g_sq2[tid] * invn - mu * mu, 0.f);
        float sc  = rsqrtf(var + 1e-5f) * gamma[tid];
        saff[tid]       = sc;
        saff[DIM + tid] = beta[tid] - mu * sc;
    }
    __syncthreads();
    if (tid == 0) {
        __threadfence();
        int old = atomicAdd(&g_cnt2, 1);
        s_last = (old == nBLK - 1);
    }
    __syncthreads();
    if (s_last) {
        if (tid < DIM) { g_sum2[tid] = 0.f; g_sq2[tid] = 0.f; }
        if (tid == 0) g_cnt2 = 0;
    }

    int i = blockIdx.x * blockDim.x + tid;
    if (i >= NNODES * 32) return;
    int n = i >> 5, c = (i & 31) * 4;
    float4 v  = *(const float4*)(g_z + (size_t)n * DIM + c);
    float4 sc = *(const float4*)(saff + c);
    float4 sh = *(const float4*)(saff + DIM + c);
    v.x = fmaf(v.x, sc.x, sh.x);
    v.y = fmaf(v.y, sc.y, sh.y);
    v.z = fmaf(v.z, sc.z, sh.z);
    v.w = fmaf(v.w, sc.w, sh.w);
    if (relu) {
        v.x = fmaxf(v.x, 0.f); v.y = fmaxf(v.y, 0.f);
        v.z = fmaxf(v.z, 0.f); v.w = fmaxf(v.w, 0.f);
    }
    *(float4*)(g_h + (size_t)n * DIM + c) = v;
    *(float4*)(g_z + (size_t)n * DIM + c) = v;
}

__global__ void k_pool(const int* __restrict__ batch, float* __restrict__ out) {
    int i = blockIdx.x * blockDim.x + threadIdx.x;
    if (i >= NNODES * 32) return;
    int n = i >> 5, c = (i & 31) * 4;
    float4 v = *(const float4*)(g_h + (size_t)n * DIM + c);
    *(float4*)(out + (size_t)NGRAPH * DIM + (size_t)n * DIM + c) = v;
    int b = __ldg(batch + n);
    red_add_v4(out + (size_t)b * DIM + c, v);
}

// ---------------- launch ----------------
extern "C" void kernel_launch(void* const* d_in, const int* in_sizes, int n_in,
                              void* d_out, int out_size) {
    const int*   batch    = (const int*)  d_in[0];
    const int*   x        = (const int*)  d_in[1];
    const int*   eidx     = (const int*)  d_in[2];
    const int*   eattr    = (const int*)  d_in[3];
    const float* atom_emb = (const float*)d_in[4];
    const float* bond_emb = (const float*)d_in[5];
    const float* W1       = (const float*)d_in[6];
    const float* b1       = (const float*)d_in[7];
    const float* g1       = (const float*)d_in[8];
    const float* be1      = (const float*)d_in[9];
    const float* W2       = (const float*)d_in[10];
    const float* b2       = (const float*)d_in[11];
    const float* gbn      = (const float*)d_in[12];
    const float* bbn      = (const float*)d_in[13];
    float* out = (float*)d_out;

    float *p_z, *p_z1, *p_sum1, *p_sq1, *p_sum2, *p_sq2;
    int *p_cnt1;
    cudaGetSymbolAddress((void**)&p_z,    g_z);
    cudaGetSymbolAddress((void**)&p_z1,   g_z1);
    cudaGetSymbolAddress((void**)&p_sum1, g_sum1);
    cudaGetSymbolAddress((void**)&p_sq1,  g_sq1);
    cudaGetSymbolAddress((void**)&p_sum2, g_sum2);
    cudaGetSymbolAddress((void**)&p_sq2,  g_sq2);
    cudaGetSymbolAddress((void**)&p_cnt1, g_cnt1);

    const int* src = eidx;
    const int* dst = eidx + NEDGE;
    const int ELEM_GRID = (NNODES * 32 + 255) / 256;
    const int G2_CTAS   = (NPAD / 128) * (DIM / 64);   // GEMM2 grid size

    k_init<<<ELEM_GRID, 256>>>(x, atom_emb, out);

    for (int i = 0; i < NLAYERS; i++) {
        k_scatter<<<NEDGE / 32, 256>>>(src, dst, eattr, bond_emb);
        k_gemm<DIM, DIM2, false><<<dim3(NPAD / 128, DIM2 / 64), 256>>>(
            p_z, W1 + (size_t)i * DIM * DIM2, b1 + (size_t)i * DIM2,
            nullptr, nullptr, nullptr, nullptr, nullptr, 0,
            p_z1, p_sum1, p_sq1);
        k_gemm<DIM2, DIM, true><<<dim3(NPAD / 128, DIM / 64), 256>>>(
            p_z1, W2 + (size_t)i * DIM2 * DIM, b2 + (size_t)i * DIM,
            p_sum1, p_sq1, g1 + (size_t)i * DIM2, be1 + (size_t)i * DIM2,
            p_cnt1, G2_CTAS,
            p_z, p_sum2, p_sq2);
        k_bnapply<<<ELEM_GRID, 256>>>(gbn + (size_t)i * DIM, bbn + (size_t)i * DIM,
                                      i < NLAYERS - 1 ? 1 : 0, ELEM_GRID);
    }

    k_pool<<<ELEM_GRID, 256>>>(batch, out);
}